// round 16
// baseline (speedup 1.0000x reference)
#include <cuda_runtime.h>
#include <cuda_bf16.h>
#include <math_constants.h>
#include <cstdint>

#define BBATCH 64
#define LLEN   512
#define DDIM   512
#define AADIM  256
#define BL     (BBATCH * LLEN)

__device__ __align__(256) __nv_bfloat16 g_S1h[(size_t)BL * DDIM];
__device__ __align__(256) __nv_bfloat16 g_S1l[(size_t)BL * DDIM];
__device__ __align__(256) __nv_bfloat16 g_S2h[(size_t)BL * DDIM];
__device__ __align__(256) __nv_bfloat16 g_S2l[(size_t)BL * DDIM];
__device__ __align__(256) __nv_bfloat16 g_Wh [(size_t)DDIM * DDIM];
__device__ __align__(256) __nv_bfloat16 g_Wl [(size_t)DDIM * DDIM];
__device__ __align__(256) __nv_bfloat16 g_Wvh[(size_t)DDIM * AADIM];
__device__ __align__(256) __nv_bfloat16 g_Wvl[(size_t)DDIM * AADIM];
__device__ __align__(256) __nv_bfloat16 g_Wqh[(size_t)DDIM * AADIM];
__device__ __align__(256) __nv_bfloat16 g_Wql[(size_t)DDIM * AADIM];
__device__ __align__(256) __nv_bfloat16 g_Th [(size_t)BL * DDIM];
__device__ __align__(256) __nv_bfloat16 g_Tl [(size_t)BL * DDIM];
__device__ __align__(256) __nv_bfloat16 g_Ch [(size_t)BBATCH * LLEN * LLEN];
__device__ __align__(256) __nv_bfloat16 g_Cl [(size_t)BBATCH * LLEN * LLEN];
__device__ __align__(256) __nv_bfloat16 g_Pbh[(size_t)BL * AADIM];
__device__ __align__(256) __nv_bfloat16 g_Pbl[(size_t)BL * AADIM];
__device__ __align__(256) __nv_bfloat16 g_Qbh[(size_t)BL * AADIM];
__device__ __align__(256) __nv_bfloat16 g_Qbl[(size_t)BL * AADIM];
__device__ __align__(256) float g_P [(size_t)BL * AADIM];
__device__ __align__(256) float g_Q [(size_t)BL * AADIM];
__device__ __align__(256) float g_Hv[(size_t)BL * AADIM];
__device__ __align__(256) float g_Hq[(size_t)BL * AADIM];

__device__ __forceinline__ uint32_t smem_u32(const void* p) {
    uint32_t a;
    asm("{ .reg .u64 t; cvta.to.shared.u64 t, %1; cvt.u32.u64 %0, t; }"
        : "=r"(a) : "l"(p));
    return a;
}
__device__ __forceinline__ uint32_t pk(__nv_bfloat16 a, __nv_bfloat16 b) {
    __nv_bfloat162 t = __halves2bfloat162(a, b);
    return *reinterpret_cast<uint32_t*>(&t);
}
__device__ __forceinline__ void split_f(float x, __nv_bfloat16& h, __nv_bfloat16& l) {
    h = __float2bfloat16(x);
    l = __float2bfloat16(x - __bfloat162float(h));
}

#define CP16(SM, G) \
    asm volatile("cp.async.cg.shared.global [%0], [%1], 16;" :: "r"(SM), "l"(G))
#define CP_COMMIT() asm volatile("cp.async.commit_group;")
#define CP_WAIT1()  asm volatile("cp.async.wait_group 1;")

#define LDSM4(R0,R1,R2,R3,ADDR) \
    asm volatile("ldmatrix.sync.aligned.m8n8.x4.shared.b16 {%0,%1,%2,%3}, [%4];" \
        : "=r"(R0),"=r"(R1),"=r"(R2),"=r"(R3) : "r"(ADDR))
#define LDSM4T(R0,R1,R2,R3,ADDR) \
    asm volatile("ldmatrix.sync.aligned.m8n8.x4.trans.shared.b16 {%0,%1,%2,%3}, [%4];" \
        : "=r"(R0),"=r"(R1),"=r"(R2),"=r"(R3) : "r"(ADDR))

__device__ __forceinline__ void mma_bf16(float* d, const uint32_t* a, const uint32_t* b) {
    asm volatile(
        "mma.sync.aligned.m16n8k16.row.col.f32.bf16.bf16.f32 "
        "{%0,%1,%2,%3}, {%4,%5,%6,%7}, {%8,%9}, {%0,%1,%2,%3};"
        : "+f"(d[0]), "+f"(d[1]), "+f"(d[2]), "+f"(d[3])
        : "r"(a[0]), "r"(a[1]), "r"(a[2]), "r"(a[3]), "r"(b[0]), "r"(b[1]));
}

__device__ __forceinline__ uint32_t swz64(int r, int ch) {
    return (uint32_t)(r * 64 + ((ch ^ (r & 3) ^ ((r >> 2) & 1)) << 4));
}
__device__ __forceinline__ uint32_t swz256(int r, int ch) {
    return (uint32_t)(r * 256 + ((ch ^ (r & 15)) << 4));
}

#define STG      32768
#define SM_BYTES 98304

__device__ __forceinline__ void stage_n(uint32_t sdst, const __nv_bfloat16* src,
                                        int rowbase, int ld, int kc, int tid)
{
    #pragma unroll
    for (int q = 0; q < 2; q++) {
        int idx = tid + q * 256;
        int r = idx >> 2, c = idx & 3;
        uint32_t sa = sdst + swz64(r, c);
        const __nv_bfloat16* g = src + (size_t)(rowbase + r) * ld + kc * 32 + c * 8;
        CP16(sa, g);
    }
}
__device__ __forceinline__ void stage_t(uint32_t sdst, const __nv_bfloat16* src,
                                        int colbase, int ld, int kc, int tid)
{
    #pragma unroll
    for (int q = 0; q < 2; q++) {
        int idx = tid + q * 256;
        int r = idx >> 4, c = idx & 15;
        uint32_t sa = sdst + swz256(r, c);
        const __nv_bfloat16* g = src + (size_t)(kc * 32 + r) * ld + colbase + c * 8;
        CP16(sa, g);
    }
}

struct GArgs {
    const __nv_bfloat16 *Ah, *Al, *Bh, *Bl;
    size_t sA, sB; int ldA, ldB;
    const float* bias; size_t sBias; int ldBias;
    float* outF; size_t sF; int ldF;
    __nv_bfloat16 *oh, *ol; size_t sO; int ldO;
};

// CTA 128x128, 8 warps 2x4 (warp 64x32), 256 thr, 2 CTAs/SM. K=512 in 16 chunks of 32.
template<int ATR, int BTR, int EPI>
__device__ __forceinline__ void gemm_body(const GArgs& G, char* smem,
                                          int bi, int bj, int z)
{
    const int tid  = threadIdx.x;
    const int lane = tid & 31, warp = tid >> 5;
    const int wm = warp >> 2, wn = warp & 3;

    const __nv_bfloat16* Ah2 = G.Ah + (size_t)z * G.sA;
    const __nv_bfloat16* Al2 = G.Al + (size_t)z * G.sA;
    const __nv_bfloat16* Bh2 = G.Bh + (size_t)z * G.sB;
    const __nv_bfloat16* Bl2 = G.Bl + (size_t)z * G.sB;
    const int ldA = G.ldA, ldB = G.ldB;

    const uint32_t su = smem_u32(smem);

    float acc[4][4][4];
    #pragma unroll
    for (int a = 0; a < 4; a++)
        #pragma unroll
        for (int b = 0; b < 4; b++)
            #pragma unroll
            for (int c = 0; c < 4; c++) acc[a][b][c] = 0.f;

    const int arow_lo   = lane & 15;
    const int achunk_ad = lane >> 4;
    const int gB        = lane >> 3;
    const int brow_lo   = ((gB >> 1) << 3) + (lane & 7);
    const int bchunk_ad = gB & 1;
    const int tg  = lane >> 3;
    const int tlr = lane & 7;

    #pragma unroll
    for (int pc = 0; pc < 2; pc++) {
        uint32_t sb = su + pc * STG;
        if (ATR) { stage_t(sb,        Ah2, bi, ldA, pc, tid);
                   stage_t(sb + 8192, Al2, bi, ldA, pc, tid); }
        else     { stage_n(sb,        Ah2, bi, ldA, pc, tid);
                   stage_n(sb + 8192, Al2, bi, ldA, pc, tid); }
        if (BTR) { stage_t(sb + 16384, Bh2, bj, ldB, pc, tid);
                   stage_t(sb + 24576, Bl2, bj, ldB, pc, tid); }
        else     { stage_n(sb + 16384, Bh2, bj, ldB, pc, tid);
                   stage_n(sb + 24576, Bl2, bj, ldB, pc, tid); }
        CP_COMMIT();
    }

    #pragma unroll 1
    for (int c = 0; c < 16; c++) {
        CP_WAIT1();
        __syncthreads();

        const uint32_t base = su + (c % 3) * STG;
        const uint32_t aB  = base;
        const uint32_t alB = base + 8192;
        const uint32_t bB  = base + 16384;
        const uint32_t blB = base + 24576;

        #pragma unroll
        for (int kb = 0; kb < 2; kb++) {
            uint32_t bh[2][2][2], blr[2][2][2];
            #pragma unroll
            for (int ng = 0; ng < 2; ng++) {
                uint32_t t0, t1, t2, t3;
                if (BTR) {
                    int k  = kb * 16 + ((tg & 1) << 3) + tlr;
                    int cn = (wn * 32 + ng * 16) / 8 + (tg >> 1);
                    uint32_t off = swz256(k, cn);
                    LDSM4T(t0, t1, t2, t3, bB + off);
                    bh[ng][0][0] = t0; bh[ng][0][1] = t1;
                    bh[ng][1][0] = t2; bh[ng][1][1] = t3;
                    LDSM4T(t0, t1, t2, t3, blB + off);
                    blr[ng][0][0] = t0; blr[ng][0][1] = t1;
                    blr[ng][1][0] = t2; blr[ng][1][1] = t3;
                } else {
                    int row = wn * 32 + ng * 16 + brow_lo;
                    uint32_t off = swz64(row, kb * 2 + bchunk_ad);
                    LDSM4(t0, t1, t2, t3, bB + off);
                    bh[ng][0][0] = t0; bh[ng][0][1] = t1;
                    bh[ng][1][0] = t2; bh[ng][1][1] = t3;
                    LDSM4(t0, t1, t2, t3, blB + off);
                    blr[ng][0][0] = t0; blr[ng][0][1] = t1;
                    blr[ng][1][0] = t2; blr[ng][1][1] = t3;
                }
            }
            #pragma unroll
            for (int mi = 0; mi < 4; mi++) {
                uint32_t ah[4], al[4];
                if (ATR) {
                    int k  = kb * 16 + ((tg >> 1) << 3) + tlr;
                    int cm = (wm * 64 + mi * 16) / 8 + (tg & 1);
                    uint32_t off = swz256(k, cm);
                    LDSM4T(ah[0], ah[1], ah[2], ah[3], aB  + off);
                    LDSM4T(al[0], al[1], al[2], al[3], alB + off);
                } else {
                    int row = wm * 64 + mi * 16 + arow_lo;
                    uint32_t off = swz64(row, kb * 2 + achunk_ad);
                    LDSM4(ah[0], ah[1], ah[2], ah[3], aB  + off);
                    LDSM4(al[0], al[1], al[2], al[3], alB + off);
                }
                #pragma unroll
                for (int ng = 0; ng < 2; ng++)
                    #pragma unroll
                    for (int nn = 0; nn < 2; nn++) {
                        int ni = ng * 2 + nn;
                        mma_bf16(acc[mi][ni], ah, bh[ng][nn]);
                        mma_bf16(acc[mi][ni], ah, blr[ng][nn]);
                        mma_bf16(acc[mi][ni], al, bh[ng][nn]);
                    }
            }
            if (kb == 0) {
                if (c + 2 < 16) {
                    uint32_t sb = su + ((c + 2) % 3) * STG;
                    if (ATR) { stage_t(sb,        Ah2, bi, ldA, c + 2, tid);
                               stage_t(sb + 8192, Al2, bi, ldA, c + 2, tid); }
                    else     { stage_n(sb,        Ah2, bi, ldA, c + 2, tid);
                               stage_n(sb + 8192, Al2, bi, ldA, c + 2, tid); }
                    if (BTR) { stage_t(sb + 16384, Bh2, bj, ldB, c + 2, tid);
                               stage_t(sb + 24576, Bl2, bj, ldB, c + 2, tid); }
                    else     { stage_n(sb + 16384, Bh2, bj, ldB, c + 2, tid);
                               stage_n(sb + 24576, Bl2, bj, ldB, c + 2, tid); }
                }
                CP_COMMIT();
            }
        }
    }

    // ---- epilogue (all natural [i][j]) ----
    const int trow = lane >> 2;
    const int tcol = (lane & 3) * 2;

    const float* bias = (EPI == 3) ? G.bias + (size_t)z * G.sBias : nullptr;
    float* outF = G.outF ? G.outF + (size_t)z * G.sF : nullptr;
    __nv_bfloat16* oh = G.oh ? G.oh + (size_t)z * G.sO : nullptr;
    __nv_bfloat16* ol = G.ol ? G.ol + (size_t)z * G.sO : nullptr;

    #pragma unroll
    for (int mi = 0; mi < 4; mi++)
        #pragma unroll
        for (int ni = 0; ni < 4; ni++) {
            int j = bj + wn * 32 + ni * 8 + tcol;
            #pragma unroll
            for (int hf = 0; hf < 2; hf++) {
                int i = bi + wm * 64 + mi * 16 + trow + hf * 8;
                float x0 = acc[mi][ni][hf * 2 + 0];
                float x1 = acc[mi][ni][hf * 2 + 1];
                if (EPI == 3) {
                    float2 bv = *(const float2*)&bias[(size_t)i * G.ldBias + j];
                    x0 = tanhf(x0 + bv.x); x1 = tanhf(x1 + bv.y);
                } else if (EPI == 2) {
                    x0 = tanhf(x0); x1 = tanhf(x1);
                }
                if (EPI == 0 || EPI == 1 || EPI == 2) {
                    __nv_bfloat16 h0, l0, h1, l1;
                    split_f(x0, h0, l0); split_f(x1, h1, l1);
                    *(uint32_t*)&oh[(size_t)i * G.ldO + j] = pk(h0, h1);
                    *(uint32_t*)&ol[(size_t)i * G.ldO + j] = pk(l0, l1);
                }
                if (EPI == 1 || EPI == 3) {
                    float2 o; o.x = x0; o.y = x1;
                    *(float2*)&outF[(size_t)i * G.ldF + j] = o;
                }
            }
        }
}

// ---------------- GEMM kernels ----------------------------------------------------
// G1 alone: grid (256, 1, 4); bj = z*128
__global__ void __launch_bounds__(256, 2)
gemm1(GArgs g)
{
    extern __shared__ char smem[];
    gemm_body<0,1,0>(g, smem, blockIdx.x * 128, blockIdx.z * 128, 0);
}

// G2 (z<2) + G3 (z>=2): grid (256, 1, 4)
__global__ void __launch_bounds__(256, 2)
mega23(GArgs g2, GArgs g3)
{
    extern __shared__ char smem[];
    int z = blockIdx.z, bi = blockIdx.x * 128;
    if (z < 2) gemm_body<0,1,1>(g2, smem, bi, z * 128, 0);
    else       gemm_body<0,1,1>(g3, smem, bi, (z - 2) * 128, 0);
}

__global__ void __launch_bounds__(256, 2)
gemm4(GArgs g)
{
    extern __shared__ char smem[];
    gemm_body<0,0,2>(g, smem, blockIdx.x * 128, blockIdx.y * 128, blockIdx.z);
}

__global__ void __launch_bounds__(256, 2)
mega56(GArgs g5, GArgs g6)
{
    extern __shared__ char smem[];
    int z = blockIdx.z, bi = blockIdx.x * 128, bj = blockIdx.y * 128;
    if (z < 64) gemm_body<0,1,3>(g5, smem, bi, bj, z);
    else        gemm_body<1,1,3>(g6, smem, bi, bj, z - 64);
}

// ---------------- single merged prep kernel --------------------------------------
struct SplitJob { const float4* in; uint2 *hi, *lo; int n4; };

__global__ void __launch_bounds__(256)
split_all(SplitJob s1, SplitJob s2, SplitJob w, SplitJob wv, SplitJob wq)
{
    int i = blockIdx.x * 256 + threadIdx.x;
    SplitJob j;
    if (i < s1.n4)                            { j = s1; }
    else if ((i -= s1.n4) < s2.n4)            { j = s2; }
    else if ((i -= s2.n4) < w.n4)             { j = w; }
    else if ((i -= w.n4) < wv.n4)             { j = wv; }
    else if ((i -= wv.n4) < wq.n4)            { j = wq; }
    else return;
    float4 v = j.in[i];
    __nv_bfloat16 h0,h1_,h2_,h3,l0,l1_,l2_,l3;
    split_f(v.x,h0,l0); split_f(v.y,h1_,l1_); split_f(v.z,h2_,l2_); split_f(v.w,h3,l3);
    j.hi[i] = make_uint2(pk(h0,h1_), pk(h2_,h3));
    j.lo[i] = make_uint2(pk(l0,l1_), pk(l2_,l3));
}

// ---------------- masked softmax + pooling ---------------------------------------
__device__ __forceinline__ float block_sum(float v, float* red) {
    int lane = threadIdx.x & 31, warp = threadIdx.x >> 5;
    #pragma unroll
    for (int o = 16; o; o >>= 1) v += __shfl_xor_sync(0xffffffffu, v, o);
    if (lane == 0) red[warp] = v;
    __syncthreads();
    float t = 0.f;
    #pragma unroll
    for (int i = 0; i < 8; i++) t += red[i];
    __syncthreads();
    return t;
}
__device__ __forceinline__ float block_max(float v, float* red) {
    int lane = threadIdx.x & 31, warp = threadIdx.x >> 5;
    #pragma unroll
    for (int o = 16; o; o >>= 1) v = fmaxf(v, __shfl_xor_sync(0xffffffffu, v, o));
    if (lane == 0) red[warp] = v;
    __syncthreads();
    float t = red[0];
    #pragma unroll
    for (int i = 1; i < 8; i++) t = fmaxf(t, red[i]);
    __syncthreads();
    return t;
}

__global__ void __launch_bounds__(256)
attn_pool2(const float* __restrict__ Hv, const float* __restrict__ whv,
           const int* __restrict__ m1, const float* __restrict__ S1,
           const float* __restrict__ Hq, const float* __restrict__ whq,
           const int* __restrict__ m2, const float* __restrict__ S2,
           float* __restrict__ out)
{
    __shared__ float sw[AADIM];
    __shared__ float sl[LLEN];
    __shared__ float smk[LLEN];
    __shared__ float red[8];

    const int idx = blockIdx.x;
    const int sel = idx >> 7;
    const int b   = (idx >> 1) & 63;
    const int dh  = idx & 1;
    const float* H = sel ? Hq : Hv;
    const float* w = sel ? whq : whv;
    const int* mask = sel ? m2 : m1;
    const float* X = sel ? S2 : S1;
    float* o = out + (size_t)sel * BBATCH * DDIM;

    const int tid = threadIdx.x;
    const int lane = tid & 31, warp = tid >> 5;

    for (int a = tid; a < AADIM; a += 256) sw[a] = w[a];
    for (int l = tid; l < LLEN; l += 256) smk[l] = (float)mask[b * LLEN + l];
    __syncthreads();

    for (int l = warp; l < LLEN; l += 8) {
        const float* Hr = H + ((size_t)b * LLEN + l) * AADIM;
        float s = 0.f;
        #pragma unroll
        for (int a = lane; a < AADIM; a += 32) s = fmaf(Hr[a], sw[a], s);
        #pragma unroll
        for (int o2 = 16; o2; o2 >>= 1) s += __shfl_down_sync(0xffffffffu, s, o2);
        if (lane == 0) sl[l] = s * smk[l];
    }
    __syncthreads();

    float m = -CUDART_INF_F;
    for (int l = tid; l < LLEN; l += 256) m = fmaxf(m, sl[l]);
    m = block_max(m, red);

    float psum = 0.f;
    for (int l = tid; l < LLEN; l += 256) {
        float e = expf(sl[l] - m);
        sl[l] = e; psum += e;
    }
    psum = block_sum(psum, red);
    float inv = 1.f / psum;

    float rsum = 0.f;
    for (int l = tid; l < LLEN; l += 256) {
        float r = sl[l] * inv * smk[l];
        sl[l] = r; rsum += r;
    }
    rsum = block_sum(rsum, red);
    float sc = 1.f / (rsum + 1e-13f);
    for (int l = tid; l < LLEN; l += 256) sl[l] *= sc;
    __syncthreads();

    const int d = dh * 256 + tid;
    const float* Xb = X + (size_t)b * LLEN * DDIM + d;
    float acc = 0.f;
    #pragma unroll 4
    for (int l = 0; l < LLEN; l++) acc = fmaf(sl[l], Xb[(size_t)l * DDIM], acc);
    o[(size_t)b * DDIM + d] = acc;
}

// ---------------- launch -----------------------------------------------------------
extern "C" void kernel_launch(void* const* d_in, const int* in_sizes, int n_in,
                              void* d_out, int out_size)
{
    const float* S1    = (const float*)d_in[0];
    const float* S2    = (const float*)d_in[1];
    const int*   mask1 = (const int*)  d_in[2];
    const int*   mask2 = (const int*)  d_in[3];
    const float* W     = (const float*)d_in[4];
    const float* Wv    = (const float*)d_in[5];
    const float* Wq    = (const float*)d_in[6];
    const float* w_hv  = (const float*)d_in[7];
    const float* w_hq  = (const float*)d_in[8];
    float* out = (float*)d_out;

    __nv_bfloat16 *S1h,*S1l,*S2h,*S2l,*Wh,*Wl,*Wvh,*Wvl,*Wqh,*Wql;
    __nv_bfloat16 *Th,*Tl,*Ch,*Cl,*Pbh,*Pbl,*Qbh,*Qbl;
    float *P,*Q,*Hv,*Hq;
    cudaGetSymbolAddress((void**)&S1h, g_S1h);  cudaGetSymbolAddress((void**)&S1l, g_S1l);
    cudaGetSymbolAddress((void**)&S2h, g_S2h);  cudaGetSymbolAddress((void**)&S2l, g_S2l);
    cudaGetSymbolAddress((void**)&Wh,  g_Wh);   cudaGetSymbolAddress((void**)&Wl,  g_Wl);
    cudaGetSymbolAddress((void**)&Wvh, g_Wvh);  cudaGetSymbolAddress((void**)&Wvl, g_Wvl);
    cudaGetSymbolAddress((void**)&Wqh, g_Wqh);  cudaGetSymbolAddress((void**)&Wql, g_Wql);
    cudaGetSymbolAddress((void**)&Th,  g_Th);   cudaGetSymbolAddress((void**)&Tl,  g_Tl);
    cudaGetSymbolAddress((void**)&Ch,  g_Ch);   cudaGetSymbolAddress((void**)&Cl,  g_Cl);
    cudaGetSymbolAddress((void**)&Pbh, g_Pbh);  cudaGetSymbolAddress((void**)&Pbl, g_Pbl);
    cudaGetSymbolAddress((void**)&Qbh, g_Qbh);  cudaGetSymbolAddress((void**)&Qbl, g_Qbl);
    cudaGetSymbolAddress((void**)&P,   g_P);    cudaGetSymbolAddress((void**)&Q,   g_Q);
    cudaGetSymbolAddress((void**)&Hv,  g_Hv);   cudaGetSymbolAddress((void**)&Hq,  g_Hq);

    cudaFuncSetAttribute(gemm1,  cudaFuncAttributeMaxDynamicSharedMemorySize, SM_BYTES);
    cudaFuncSetAttribute(mega23, cudaFuncAttributeMaxDynamicSharedMemorySize, SM_BYTES);
    cudaFuncSetAttribute(gemm4,  cudaFuncAttributeMaxDynamicSharedMemorySize, SM_BYTES);
    cudaFuncSetAttribute(mega56, cudaFuncAttributeMaxDynamicSharedMemorySize, SM_BYTES);

    const dim3 blk(256);
    const size_t sLL = (size_t)LLEN * LLEN;
    const size_t sLA = (size_t)LLEN * AADIM;
    const size_t sLD = (size_t)LLEN * DDIM;
    const int n4 = BL * DDIM / 4;

    // fork-join resources (host-side; created per call, retained through capture)
    cudaStream_t s2;
    cudaStreamCreateWithFlags(&s2, cudaStreamNonBlocking);
    cudaEvent_t evFork, evJoin;
    cudaEventCreateWithFlags(&evFork, cudaEventDisableTiming);
    cudaEventCreateWithFlags(&evJoin, cudaEventDisableTiming);

    SplitJob js1 = { (const float4*)S1, (uint2*)S1h, (uint2*)S1l, n4 };
    SplitJob js2 = { (const float4*)S2, (uint2*)S2h, (uint2*)S2l, n4 };
    SplitJob jw  = { (const float4*)W,  (uint2*)Wh,  (uint2*)Wl,  DDIM * DDIM / 4 };
    SplitJob jwv = { (const float4*)Wv, (uint2*)Wvh, (uint2*)Wvl, DDIM * AADIM / 4 };
    SplitJob jwq = { (const float4*)Wq, (uint2*)Wqh, (uint2*)Wql, DDIM * AADIM / 4 };
    int total4 = 2 * n4 + DDIM * DDIM / 4 + 2 * (DDIM * AADIM / 4);
    split_all<<<(total4 + 255) / 256, blk>>>(js1, js2, jw, jwv, jwq);

    cudaEventRecord(evFork, 0);
    cudaStreamWaitEvent(s2, evFork, 0);

    // side stream: G2 + G3 (independent of G1/G4)
    GArgs g2 = { S1h, S1l, Wvh, Wvl, 0, 0, DDIM, AADIM,
                 nullptr, 0, 0,  P, 0, AADIM,
                 Pbh, Pbl, 0, AADIM };
    GArgs g3 = { S2h, S2l, Wqh, Wql, 0, 0, DDIM, AADIM,
                 nullptr, 0, 0,  Q, 0, AADIM,
                 Qbh, Qbl, 0, AADIM };
    mega23<<<dim3(BL/128, 1, 4), blk, SM_BYTES, s2>>>(g2, g3);
    cudaEventRecord(evJoin, s2);

    // main stream: G1 -> G4
    GArgs g1 = { S1h, S1l, Wh, Wl, 0, 0, DDIM, DDIM,
                 nullptr, 0, 0,  nullptr, 0, 0,
                 Th, Tl, 0, DDIM };
    gemm1<<<dim3(BL/128, 1, 4), blk, SM_BYTES>>>(g1);

    GArgs g4 = { Th, Tl, S2h, S2l, sLD, sLD, DDIM, DDIM,
                 nullptr, 0, 0,  nullptr, 0, 0,
                 Ch, Cl, sLL, LLEN };
    gemm4<<<dim3(LLEN/128, LLEN/128, BBATCH), blk, SM_BYTES>>>(g4);

    // join: mega56 needs G4 (main) + G2/G3 (side)
    cudaStreamWaitEvent(0, evJoin, 0);

    GArgs g5 = { Ch, Cl, Qbh, Qbl, sLL, sLA, LLEN, AADIM,
                 P, sLA, AADIM,  Hv, sLA, AADIM,
                 nullptr, nullptr, 0, 0 };
    GArgs g6 = { Ch, Cl, Pbh, Pbl, sLL, sLA, LLEN, AADIM,
                 Q, sLA, AADIM,  Hq, sLA, AADIM,
                 nullptr, nullptr, 0, 0 };
    mega56<<<dim3(LLEN/128, AADIM/128, 128), blk, SM_BYTES>>>(g5, g6);

    attn_pool2<<<256, blk>>>(Hv, w_hv, mask1, S1, Hq, w_hq, mask2, S2, out);
}

// round 17
// speedup vs baseline: 1.0860x; 1.0860x over previous
#include <cuda_runtime.h>
#include <cuda_bf16.h>
#include <math_constants.h>
#include <cstdint>

#define BBATCH 64
#define LLEN   512
#define DDIM   512
#define AADIM  256
#define BL     (BBATCH * LLEN)

__device__ __align__(256) __nv_bfloat16 g_S1h[(size_t)BL * DDIM];
__device__ __align__(256) __nv_bfloat16 g_S1l[(size_t)BL * DDIM];
__device__ __align__(256) __nv_bfloat16 g_S2h[(size_t)BL * DDIM];
__device__ __align__(256) __nv_bfloat16 g_S2l[(size_t)BL * DDIM];
__device__ __align__(256) __nv_bfloat16 g_Wh [(size_t)DDIM * DDIM];
__device__ __align__(256) __nv_bfloat16 g_Wl [(size_t)DDIM * DDIM];
__device__ __align__(256) __nv_bfloat16 g_Wvh[(size_t)DDIM * AADIM];
__device__ __align__(256) __nv_bfloat16 g_Wvl[(size_t)DDIM * AADIM];
__device__ __align__(256) __nv_bfloat16 g_Wqh[(size_t)DDIM * AADIM];
__device__ __align__(256) __nv_bfloat16 g_Wql[(size_t)DDIM * AADIM];
__device__ __align__(256) __nv_bfloat16 g_Th [(size_t)BL * DDIM];
__device__ __align__(256) __nv_bfloat16 g_Tl [(size_t)BL * DDIM];
__device__ __align__(256) __nv_bfloat16 g_Ch [(size_t)BBATCH * LLEN * LLEN];
__device__ __align__(256) __nv_bfloat16 g_Cl [(size_t)BBATCH * LLEN * LLEN];
__device__ __align__(256) __nv_bfloat16 g_Pbh[(size_t)BL * AADIM];
__device__ __align__(256) __nv_bfloat16 g_Pbl[(size_t)BL * AADIM];
__device__ __align__(256) __nv_bfloat16 g_Qbh[(size_t)BL * AADIM];
__device__ __align__(256) __nv_bfloat16 g_Qbl[(size_t)BL * AADIM];
__device__ __align__(256) float g_P [(size_t)BL * AADIM];
__device__ __align__(256) float g_Q [(size_t)BL * AADIM];
__device__ __align__(256) float g_Hv[(size_t)BL * AADIM];
__device__ __align__(256) float g_Hq[(size_t)BL * AADIM];
__device__ __align__(256) float g_attn[2 * BBATCH * LLEN];

__device__ __forceinline__ uint32_t smem_u32(const void* p) {
    uint32_t a;
    asm("{ .reg .u64 t; cvta.to.shared.u64 t, %1; cvt.u32.u64 %0, t; }"
        : "=r"(a) : "l"(p));
    return a;
}
__device__ __forceinline__ uint32_t pk(__nv_bfloat16 a, __nv_bfloat16 b) {
    __nv_bfloat162 t = __halves2bfloat162(a, b);
    return *reinterpret_cast<uint32_t*>(&t);
}
__device__ __forceinline__ void split_f(float x, __nv_bfloat16& h, __nv_bfloat16& l) {
    h = __float2bfloat16(x);
    l = __float2bfloat16(x - __bfloat162float(h));
}

#define CP16(SM, G) \
    asm volatile("cp.async.cg.shared.global [%0], [%1], 16;" :: "r"(SM), "l"(G))
#define CP_COMMIT() asm volatile("cp.async.commit_group;")
#define CP_WAIT1()  asm volatile("cp.async.wait_group 1;")

#define LDSM4(R0,R1,R2,R3,ADDR) \
    asm volatile("ldmatrix.sync.aligned.m8n8.x4.shared.b16 {%0,%1,%2,%3}, [%4];" \
        : "=r"(R0),"=r"(R1),"=r"(R2),"=r"(R3) : "r"(ADDR))
#define LDSM4T(R0,R1,R2,R3,ADDR) \
    asm volatile("ldmatrix.sync.aligned.m8n8.x4.trans.shared.b16 {%0,%1,%2,%3}, [%4];" \
        : "=r"(R0),"=r"(R1),"=r"(R2),"=r"(R3) : "r"(ADDR))

__device__ __forceinline__ void mma_bf16(float* d, const uint32_t* a, const uint32_t* b) {
    asm volatile(
        "mma.sync.aligned.m16n8k16.row.col.f32.bf16.bf16.f32 "
        "{%0,%1,%2,%3}, {%4,%5,%6,%7}, {%8,%9}, {%0,%1,%2,%3};"
        : "+f"(d[0]), "+f"(d[1]), "+f"(d[2]), "+f"(d[3])
        : "r"(a[0]), "r"(a[1]), "r"(a[2]), "r"(a[3]), "r"(b[0]), "r"(b[1]));
}

__device__ __forceinline__ uint32_t swz64(int r, int ch) {
    return (uint32_t)(r * 64 + ((ch ^ (r & 3) ^ ((r >> 2) & 1)) << 4));
}
__device__ __forceinline__ uint32_t swz256(int r, int ch) {
    return (uint32_t)(r * 256 + ((ch ^ (r & 15)) << 4));
}

#define STG      32768
#define SM_BYTES 98304

__device__ __forceinline__ void stage_n(uint32_t sdst, const __nv_bfloat16* src,
                                        int rowbase, int ld, int kc, int tid)
{
    #pragma unroll
    for (int q = 0; q < 2; q++) {
        int idx = tid + q * 256;
        int r = idx >> 2, c = idx & 3;
        uint32_t sa = sdst + swz64(r, c);
        const __nv_bfloat16* g = src + (size_t)(rowbase + r) * ld + kc * 32 + c * 8;
        CP16(sa, g);
    }
}
__device__ __forceinline__ void stage_t(uint32_t sdst, const __nv_bfloat16* src,
                                        int colbase, int ld, int kc, int tid)
{
    #pragma unroll
    for (int q = 0; q < 2; q++) {
        int idx = tid + q * 256;
        int r = idx >> 4, c = idx & 15;
        uint32_t sa = sdst + swz256(r, c);
        const __nv_bfloat16* g = src + (size_t)(kc * 32 + r) * ld + colbase + c * 8;
        CP16(sa, g);
    }
}

struct GArgs {
    const __nv_bfloat16 *Ah, *Al, *Bh, *Bl;
    size_t sA, sB; int ldA, ldB;
    const float* bias; size_t sBias; int ldBias;
    float* outF; size_t sF; int ldF;
    __nv_bfloat16 *oh, *ol; size_t sO; int ldO;
};

// CTA 128x128, 8 warps 2x4 (warp 64x32), 256 thr, 2 CTAs/SM. K=512 in 16 chunks of 32.
template<int ATR, int BTR, int EPI>
__device__ __forceinline__ void gemm_body(const GArgs& G, char* smem,
                                          int bi, int bj, int z)
{
    const int tid  = threadIdx.x;
    const int lane = tid & 31, warp = tid >> 5;
    const int wm = warp >> 2, wn = warp & 3;

    const __nv_bfloat16* Ah2 = G.Ah + (size_t)z * G.sA;
    const __nv_bfloat16* Al2 = G.Al + (size_t)z * G.sA;
    const __nv_bfloat16* Bh2 = G.Bh + (size_t)z * G.sB;
    const __nv_bfloat16* Bl2 = G.Bl + (size_t)z * G.sB;
    const int ldA = G.ldA, ldB = G.ldB;

    const uint32_t su = smem_u32(smem);

    float acc[4][4][4];
    #pragma unroll
    for (int a = 0; a < 4; a++)
        #pragma unroll
        for (int b = 0; b < 4; b++)
            #pragma unroll
            for (int c = 0; c < 4; c++) acc[a][b][c] = 0.f;

    const int arow_lo   = lane & 15;
    const int achunk_ad = lane >> 4;
    const int gB        = lane >> 3;
    const int brow_lo   = ((gB >> 1) << 3) + (lane & 7);
    const int bchunk_ad = gB & 1;
    const int tg  = lane >> 3;
    const int tlr = lane & 7;

    #pragma unroll
    for (int pc = 0; pc < 2; pc++) {
        uint32_t sb = su + pc * STG;
        if (ATR) { stage_t(sb,        Ah2, bi, ldA, pc, tid);
                   stage_t(sb + 8192, Al2, bi, ldA, pc, tid); }
        else     { stage_n(sb,        Ah2, bi, ldA, pc, tid);
                   stage_n(sb + 8192, Al2, bi, ldA, pc, tid); }
        if (BTR) { stage_t(sb + 16384, Bh2, bj, ldB, pc, tid);
                   stage_t(sb + 24576, Bl2, bj, ldB, pc, tid); }
        else     { stage_n(sb + 16384, Bh2, bj, ldB, pc, tid);
                   stage_n(sb + 24576, Bl2, bj, ldB, pc, tid); }
        CP_COMMIT();
    }

    #pragma unroll 1
    for (int c = 0; c < 16; c++) {
        CP_WAIT1();
        __syncthreads();

        const uint32_t base = su + (c % 3) * STG;
        const uint32_t aB  = base;
        const uint32_t alB = base + 8192;
        const uint32_t bB  = base + 16384;
        const uint32_t blB = base + 24576;

        #pragma unroll
        for (int kb = 0; kb < 2; kb++) {
            uint32_t bh[2][2][2], blr[2][2][2];
            #pragma unroll
            for (int ng = 0; ng < 2; ng++) {
                uint32_t t0, t1, t2, t3;
                if (BTR) {
                    int k  = kb * 16 + ((tg & 1) << 3) + tlr;
                    int cn = (wn * 32 + ng * 16) / 8 + (tg >> 1);
                    uint32_t off = swz256(k, cn);
                    LDSM4T(t0, t1, t2, t3, bB + off);
                    bh[ng][0][0] = t0; bh[ng][0][1] = t1;
                    bh[ng][1][0] = t2; bh[ng][1][1] = t3;
                    LDSM4T(t0, t1, t2, t3, blB + off);
                    blr[ng][0][0] = t0; blr[ng][0][1] = t1;
                    blr[ng][1][0] = t2; blr[ng][1][1] = t3;
                } else {
                    int row = wn * 32 + ng * 16 + brow_lo;
                    uint32_t off = swz64(row, kb * 2 + bchunk_ad);
                    LDSM4(t0, t1, t2, t3, bB + off);
                    bh[ng][0][0] = t0; bh[ng][0][1] = t1;
                    bh[ng][1][0] = t2; bh[ng][1][1] = t3;
                    LDSM4(t0, t1, t2, t3, blB + off);
                    blr[ng][0][0] = t0; blr[ng][0][1] = t1;
                    blr[ng][1][0] = t2; blr[ng][1][1] = t3;
                }
            }
            #pragma unroll
            for (int mi = 0; mi < 4; mi++) {
                uint32_t ah[4], al[4];
                if (ATR) {
                    int k  = kb * 16 + ((tg >> 1) << 3) + tlr;
                    int cm = (wm * 64 + mi * 16) / 8 + (tg & 1);
                    uint32_t off = swz256(k, cm);
                    LDSM4T(ah[0], ah[1], ah[2], ah[3], aB  + off);
                    LDSM4T(al[0], al[1], al[2], al[3], alB + off);
                } else {
                    int row = wm * 64 + mi * 16 + arow_lo;
                    uint32_t off = swz64(row, kb * 2 + achunk_ad);
                    LDSM4(ah[0], ah[1], ah[2], ah[3], aB  + off);
                    LDSM4(al[0], al[1], al[2], al[3], alB + off);
                }
                #pragma unroll
                for (int ng = 0; ng < 2; ng++)
                    #pragma unroll
                    for (int nn = 0; nn < 2; nn++) {
                        int ni = ng * 2 + nn;
                        mma_bf16(acc[mi][ni], ah, bh[ng][nn]);
                        mma_bf16(acc[mi][ni], ah, blr[ng][nn]);
                        mma_bf16(acc[mi][ni], al, bh[ng][nn]);
                    }
            }
            if (kb == 0) {
                if (c + 2 < 16) {
                    uint32_t sb = su + ((c + 2) % 3) * STG;
                    if (ATR) { stage_t(sb,        Ah2, bi, ldA, c + 2, tid);
                               stage_t(sb + 8192, Al2, bi, ldA, c + 2, tid); }
                    else     { stage_n(sb,        Ah2, bi, ldA, c + 2, tid);
                               stage_n(sb + 8192, Al2, bi, ldA, c + 2, tid); }
                    if (BTR) { stage_t(sb + 16384, Bh2, bj, ldB, c + 2, tid);
                               stage_t(sb + 24576, Bl2, bj, ldB, c + 2, tid); }
                    else     { stage_n(sb + 16384, Bh2, bj, ldB, c + 2, tid);
                               stage_n(sb + 24576, Bl2, bj, ldB, c + 2, tid); }
                }
                CP_COMMIT();
            }
        }
    }

    // ---- epilogue (all natural [i][j]) ----
    const int trow = lane >> 2;
    const int tcol = (lane & 3) * 2;

    const float* bias = (EPI == 3) ? G.bias + (size_t)z * G.sBias : nullptr;
    float* outF = G.outF ? G.outF + (size_t)z * G.sF : nullptr;
    __nv_bfloat16* oh = G.oh ? G.oh + (size_t)z * G.sO : nullptr;
    __nv_bfloat16* ol = G.ol ? G.ol + (size_t)z * G.sO : nullptr;

    #pragma unroll
    for (int mi = 0; mi < 4; mi++)
        #pragma unroll
        for (int ni = 0; ni < 4; ni++) {
            int j = bj + wn * 32 + ni * 8 + tcol;
            #pragma unroll
            for (int hf = 0; hf < 2; hf++) {
                int i = bi + wm * 64 + mi * 16 + trow + hf * 8;
                float x0 = acc[mi][ni][hf * 2 + 0];
                float x1 = acc[mi][ni][hf * 2 + 1];
                if (EPI == 3) {
                    float2 bv = *(const float2*)&bias[(size_t)i * G.ldBias + j];
                    x0 = tanhf(x0 + bv.x); x1 = tanhf(x1 + bv.y);
                } else if (EPI == 2) {
                    x0 = tanhf(x0); x1 = tanhf(x1);
                }
                if (EPI == 0 || EPI == 1 || EPI == 2) {
                    __nv_bfloat16 h0, l0, h1, l1;
                    split_f(x0, h0, l0); split_f(x1, h1, l1);
                    *(uint32_t*)&oh[(size_t)i * G.ldO + j] = pk(h0, h1);
                    *(uint32_t*)&ol[(size_t)i * G.ldO + j] = pk(l0, l1);
                }
                if (EPI == 1 || EPI == 3) {
                    float2 o; o.x = x0; o.y = x1;
                    *(float2*)&outF[(size_t)i * G.ldF + j] = o;
                }
            }
        }
}

// ---------------- merged GEMM kernels -------------------------------------------
__global__ void __launch_bounds__(256, 2)
mega123(GArgs g1, GArgs g2, GArgs g3)
{
    extern __shared__ char smem[];
    int z = blockIdx.z, bi = blockIdx.x * 128;
    if (z < 4)      gemm_body<0,1,0>(g1, smem, bi, z * 128, 0);
    else if (z < 6) gemm_body<0,1,1>(g2, smem, bi, (z - 4) * 128, 0);
    else            gemm_body<0,1,1>(g3, smem, bi, (z - 6) * 128, 0);
}

__global__ void __launch_bounds__(256, 2)
gemm4(GArgs g)
{
    extern __shared__ char smem[];
    gemm_body<0,0,2>(g, smem, blockIdx.x * 128, blockIdx.y * 128, blockIdx.z);
}

__global__ void __launch_bounds__(256, 2)
mega56(GArgs g5, GArgs g6)
{
    extern __shared__ char smem[];
    int z = blockIdx.z, bi = blockIdx.x * 128, bj = blockIdx.y * 128;
    if (z < 64) gemm_body<0,1,3>(g5, smem, bi, bj, z);
    else        gemm_body<1,1,3>(g6, smem, bi, bj, z - 64);
}

// ---------------- single merged prep kernel --------------------------------------
struct SplitJob { const float4* in; uint2 *hi, *lo; int n4; };

__global__ void __launch_bounds__(256)
split_all(SplitJob s1, SplitJob s2, SplitJob w, SplitJob wv, SplitJob wq)
{
    int i = blockIdx.x * 256 + threadIdx.x;
    SplitJob j;
    if (i < s1.n4)                            { j = s1; }
    else if ((i -= s1.n4) < s2.n4)            { j = s2; }
    else if ((i -= s2.n4) < w.n4)             { j = w; }
    else if ((i -= w.n4) < wv.n4)             { j = wv; }
    else if ((i -= wv.n4) < wq.n4)            { j = wq; }
    else return;
    float4 v = j.in[i];
    __nv_bfloat16 h0,h1_,h2_,h3,l0,l1_,l2_,l3;
    split_f(v.x,h0,l0); split_f(v.y,h1_,l1_); split_f(v.z,h2_,l2_); split_f(v.w,h3,l3);
    j.hi[i] = make_uint2(pk(h0,h1_), pk(h2_,h3));
    j.lo[i] = make_uint2(pk(l0,l1_), pk(l2_,l3));
}

// ---------------- masked softmax (attn weights only) ------------------------------
__device__ __forceinline__ float block_sum(float v, float* red) {
    int lane = threadIdx.x & 31, warp = threadIdx.x >> 5;
    #pragma unroll
    for (int o = 16; o; o >>= 1) v += __shfl_xor_sync(0xffffffffu, v, o);
    if (lane == 0) red[warp] = v;
    __syncthreads();
    float t = 0.f;
    #pragma unroll
    for (int i = 0; i < 8; i++) t += red[i];
    __syncthreads();
    return t;
}
__device__ __forceinline__ float block_max(float v, float* red) {
    int lane = threadIdx.x & 31, warp = threadIdx.x >> 5;
    #pragma unroll
    for (int o = 16; o; o >>= 1) v = fmaxf(v, __shfl_xor_sync(0xffffffffu, v, o));
    if (lane == 0) red[warp] = v;
    __syncthreads();
    float t = red[0];
    #pragma unroll
    for (int i = 1; i < 8; i++) t = fmaxf(t, red[i]);
    __syncthreads();
    return t;
}

// grid 128 = sel*64 + b
__global__ void __launch_bounds__(256)
attn_k(const float* __restrict__ Hv, const float* __restrict__ whv,
       const int* __restrict__ m1,
       const float* __restrict__ Hq, const float* __restrict__ whq,
       const int* __restrict__ m2,
       float* __restrict__ attn)
{
    __shared__ float sw[AADIM];
    __shared__ float sl[LLEN];
    __shared__ float smk[LLEN];
    __shared__ float red[8];

    const int sel = blockIdx.x >> 6;
    const int b   = blockIdx.x & 63;
    const float* H = sel ? Hq : Hv;
    const float* w = sel ? whq : whv;
    const int* mask = sel ? m2 : m1;

    const int tid = threadIdx.x;
    const int lane = tid & 31, warp = tid >> 5;

    for (int a = tid; a < AADIM; a += 256) sw[a] = w[a];
    for (int l = tid; l < LLEN; l += 256) smk[l] = (float)mask[b * LLEN + l];
    __syncthreads();

    for (int l = warp; l < LLEN; l += 8) {
        const float* Hr = H + ((size_t)b * LLEN + l) * AADIM;
        float s = 0.f;
        #pragma unroll
        for (int a = lane; a < AADIM; a += 32) s = fmaf(Hr[a], sw[a], s);
        #pragma unroll
        for (int o2 = 16; o2; o2 >>= 1) s += __shfl_down_sync(0xffffffffu, s, o2);
        if (lane == 0) sl[l] = s * smk[l];
    }
    __syncthreads();

    float m = -CUDART_INF_F;
    for (int l = tid; l < LLEN; l += 256) m = fmaxf(m, sl[l]);
    m = block_max(m, red);

    float psum = 0.f;
    for (int l = tid; l < LLEN; l += 256) {
        float e = expf(sl[l] - m);
        sl[l] = e; psum += e;
    }
    psum = block_sum(psum, red);
    float inv = 1.f / psum;

    float rsum = 0.f;
    for (int l = tid; l < LLEN; l += 256) {
        float r = sl[l] * inv * smk[l];
        sl[l] = r; rsum += r;
    }
    rsum = block_sum(rsum, red);
    float sc = 1.f / (rsum + 1e-13f);
    for (int l = tid; l < LLEN; l += 256)
        attn[(size_t)blockIdx.x * LLEN + l] = sl[l] * sc;
}

// grid 512 = sel*256 + b*4 + dq; block 128; pools quarter-D slice
__global__ void __launch_bounds__(128)
pool_k(const float* __restrict__ attn,
       const float* __restrict__ S1, const float* __restrict__ S2,
       float* __restrict__ out)
{
    __shared__ float sa[LLEN];
    const int idx = blockIdx.x;
    const int sel = idx >> 8;
    const int b   = (idx >> 2) & 63;
    const int dq  = idx & 3;
    const float* X = sel ? S2 : S1;
    const float* a = attn + (size_t)(sel * BBATCH + b) * LLEN;
    const int tid = threadIdx.x;

    for (int l = tid; l < LLEN; l += 128) sa[l] = a[l];
    __syncthreads();

    const int d = dq * 128 + tid;
    const float* Xb = X + (size_t)b * LLEN * DDIM + d;
    float acc = 0.f;
    #pragma unroll 8
    for (int l = 0; l < LLEN; l++) acc = fmaf(sa[l], Xb[(size_t)l * DDIM], acc);
    out[(size_t)sel * BBATCH * DDIM + (size_t)b * DDIM + d] = acc;
}

// ---------------- launch -----------------------------------------------------------
extern "C" void kernel_launch(void* const* d_in, const int* in_sizes, int n_in,
                              void* d_out, int out_size)
{
    const float* S1    = (const float*)d_in[0];
    const float* S2    = (const float*)d_in[1];
    const int*   mask1 = (const int*)  d_in[2];
    const int*   mask2 = (const int*)  d_in[3];
    const float* W     = (const float*)d_in[4];
    const float* Wv    = (const float*)d_in[5];
    const float* Wq    = (const float*)d_in[6];
    const float* w_hv  = (const float*)d_in[7];
    const float* w_hq  = (const float*)d_in[8];
    float* out = (float*)d_out;

    __nv_bfloat16 *S1h,*S1l,*S2h,*S2l,*Wh,*Wl,*Wvh,*Wvl,*Wqh,*Wql;
    __nv_bfloat16 *Th,*Tl,*Ch,*Cl,*Pbh,*Pbl,*Qbh,*Qbl;
    float *P,*Q,*Hv,*Hq,*attn;
    cudaGetSymbolAddress((void**)&S1h, g_S1h);  cudaGetSymbolAddress((void**)&S1l, g_S1l);
    cudaGetSymbolAddress((void**)&S2h, g_S2h);  cudaGetSymbolAddress((void**)&S2l, g_S2l);
    cudaGetSymbolAddress((void**)&Wh,  g_Wh);   cudaGetSymbolAddress((void**)&Wl,  g_Wl);
    cudaGetSymbolAddress((void**)&Wvh, g_Wvh);  cudaGetSymbolAddress((void**)&Wvl, g_Wvl);
    cudaGetSymbolAddress((void**)&Wqh, g_Wqh);  cudaGetSymbolAddress((void**)&Wql, g_Wql);
    cudaGetSymbolAddress((void**)&Th,  g_Th);   cudaGetSymbolAddress((void**)&Tl,  g_Tl);
    cudaGetSymbolAddress((void**)&Ch,  g_Ch);   cudaGetSymbolAddress((void**)&Cl,  g_Cl);
    cudaGetSymbolAddress((void**)&Pbh, g_Pbh);  cudaGetSymbolAddress((void**)&Pbl, g_Pbl);
    cudaGetSymbolAddress((void**)&Qbh, g_Qbh);  cudaGetSymbolAddress((void**)&Qbl, g_Qbl);
    cudaGetSymbolAddress((void**)&P,   g_P);    cudaGetSymbolAddress((void**)&Q,   g_Q);
    cudaGetSymbolAddress((void**)&Hv,  g_Hv);   cudaGetSymbolAddress((void**)&Hq,  g_Hq);
    cudaGetSymbolAddress((void**)&attn, g_attn);

    cudaFuncSetAttribute(mega123, cudaFuncAttributeMaxDynamicSharedMemorySize, SM_BYTES);
    cudaFuncSetAttribute(gemm4,   cudaFuncAttributeMaxDynamicSharedMemorySize, SM_BYTES);
    cudaFuncSetAttribute(mega56,  cudaFuncAttributeMaxDynamicSharedMemorySize, SM_BYTES);

    const dim3 blk(256);
    const size_t sLL = (size_t)LLEN * LLEN;
    const size_t sLA = (size_t)LLEN * AADIM;
    const size_t sLD = (size_t)LLEN * DDIM;
    const int n4 = BL * DDIM / 4;

    SplitJob js1 = { (const float4*)S1, (uint2*)S1h, (uint2*)S1l, n4 };
    SplitJob js2 = { (const float4*)S2, (uint2*)S2h, (uint2*)S2l, n4 };
    SplitJob jw  = { (const float4*)W,  (uint2*)Wh,  (uint2*)Wl,  DDIM * DDIM / 4 };
    SplitJob jwv = { (const float4*)Wv, (uint2*)Wvh, (uint2*)Wvl, DDIM * AADIM / 4 };
    SplitJob jwq = { (const float4*)Wq, (uint2*)Wqh, (uint2*)Wql, DDIM * AADIM / 4 };
    int total4 = 2 * n4 + DDIM * DDIM / 4 + 2 * (DDIM * AADIM / 4);
    split_all<<<(total4 + 255) / 256, blk>>>(js1, js2, jw, jwv, jwq);

    GArgs g1 = { S1h, S1l, Wh, Wl, 0, 0, DDIM, DDIM,
                 nullptr, 0, 0,  nullptr, 0, 0,
                 Th, Tl, 0, DDIM };
    GArgs g2 = { S1h, S1l, Wvh, Wvl, 0, 0, DDIM, AADIM,
                 nullptr, 0, 0,  P, 0, AADIM,
                 Pbh, Pbl, 0, AADIM };
    GArgs g3 = { S2h, S2l, Wqh, Wql, 0, 0, DDIM, AADIM,
                 nullptr, 0, 0,  Q, 0, AADIM,
                 Qbh, Qbl, 0, AADIM };
    mega123<<<dim3(BL/128, 1, 8), blk, SM_BYTES>>>(g1, g2, g3);

    GArgs g4 = { Th, Tl, S2h, S2l, sLD, sLD, DDIM, DDIM,
                 nullptr, 0, 0,  nullptr, 0, 0,
                 Ch, Cl, sLL, LLEN };
    gemm4<<<dim3(LLEN/128, LLEN/128, BBATCH), blk, SM_BYTES>>>(g4);

    GArgs g5 = { Ch, Cl, Qbh, Qbl, sLL, sLA, LLEN, AADIM,
                 P, sLA, AADIM,  Hv, sLA, AADIM,
                 nullptr, nullptr, 0, 0 };
    GArgs g6 = { Ch, Cl, Pbh, Pbl, sLL, sLA, LLEN, AADIM,
                 Q, sLA, AADIM,  Hq, sLA, AADIM,
                 nullptr, nullptr, 0, 0 };
    mega56<<<dim3(LLEN/128, AADIM/128, 128), blk, SM_BYTES>>>(g5, g6);

    attn_k<<<2 * BBATCH, blk>>>(Hv, w_hv, mask1, Hq, w_hq, mask2, attn);
    pool_k<<<512, 128>>>(attn, S1, S2, out);
}